// round 12
// baseline (speedup 1.0000x reference)
#include <cuda_runtime.h>
#include <math.h>

#define B_ 8
#define T_ 4096
#define D_ 1024
#define NCHUNK 128
#define CH (T_ / NCHUNK)        // 32 rows per k_main block
#define NBLK (B_ * NCHUNK)      // 1024 k_main blocks
#define NSUB 128                // scan sub-chunks (32 rows each)
#define CH2 (T_ / NSUB)         // 32 rows per k_partial block
#define NBLK2 (B_ * NSUB)       // 1024 k_partial blocks
#define THREADS 256             // 4 d-lanes per thread
#define G 8                     // rows per barrier group

typedef unsigned long long u64;
typedef longlong2 ll2;

// Scratch (allocation-free rule: device globals)
__device__ float2 g_cum[NBLK2 * D_];   // (sum_x, sum_sq) per (sub-chunk, d)
__device__ float  g_scal[8];           // tau, w, a1, a3, sig1, sig3, s2p, invN

__device__ __forceinline__ float tanh_fast(float x) {
    float y; asm("tanh.approx.f32 %0, %1;" : "=f"(y) : "f"(x)); return y;
}
__device__ __forceinline__ float ex2_fast(float x) {
    float y; asm("ex2.approx.f32 %0, %1;" : "=f"(y) : "f"(x)); return y;
}
__device__ __forceinline__ float lg2_fast(float x) {
    float y; asm("lg2.approx.f32 %0, %1;" : "=f"(y) : "f"(x)); return y;
}

// ---- packed f32x2 helpers (sm_103a) ----
__device__ __forceinline__ u64 pack2(float lo, float hi) {
    u64 r; asm("mov.b64 %0, {%1, %2};" : "=l"(r) : "f"(lo), "f"(hi)); return r;
}
__device__ __forceinline__ void unpack2(u64 v, float& lo, float& hi) {
    asm("mov.b64 {%0, %1}, %2;" : "=f"(lo), "=f"(hi) : "l"(v));
}
__device__ __forceinline__ u64 bcast2(float v) { return pack2(v, v); }
__device__ __forceinline__ u64 fma2(u64 a, u64 b, u64 c) {
    u64 d; asm("fma.rn.f32x2 %0, %1, %2, %3;" : "=l"(d) : "l"(a), "l"(b), "l"(c)); return d;
}
__device__ __forceinline__ u64 mul2(u64 a, u64 b) {
    u64 d; asm("mul.rn.f32x2 %0, %1, %2;" : "=l"(d) : "l"(a), "l"(b)); return d;
}
__device__ __forceinline__ u64 add2(u64 a, u64 b) {
    u64 d; asm("add.rn.f32x2 %0, %1, %2;" : "=l"(d) : "l"(a), "l"(b)); return d;
}
__device__ __forceinline__ u64 abs2(u64 a) { return a & 0x7FFFFFFF7FFFFFFFULL; }
__device__ __forceinline__ u64 neg2(u64 a) { return a ^ 0x8000000080000000ULL; }

// ---------------------------------------------------------------------------
// Kernel 1: per-sub-chunk sums of x and x^2; block 0 also computes scalars
// (round-8 winner: 26 us @ 66% DRAM)
// ---------------------------------------------------------------------------
__global__ void __launch_bounds__(THREADS) k_partial(
        const float4* __restrict__ x,
        const float* __restrict__ ema_out,
        const float* __restrict__ var_fast,
        const float* __restrict__ var_slow,
        const float* __restrict__ lt,  const float* __restrict__ ls1,
        const float* __restrict__ ls2, const float* __restrict__ ls3,
        const float* __restrict__ lw,  const float* __restrict__ la1,
        const float* __restrict__ la2, const float* __restrict__ la3) {
    int blk = blockIdx.x;
    int tid = threadIdx.x;
    long base = (long)blk * CH2 * (D_ / 4) + tid;
    float sx0 = 0.f, sx1 = 0.f, sx2 = 0.f, sx3 = 0.f;
    float sq0 = 0.f, sq1 = 0.f, sq2 = 0.f, sq3 = 0.f;
    #pragma unroll 8
    for (int r = 0; r < CH2; r++) {
        float4 v = x[base + (long)r * (D_ / 4)];
        sx0 += v.x; sx1 += v.y; sx2 += v.z; sx3 += v.w;
        sq0 = fmaf(v.x, v.x, sq0); sq1 = fmaf(v.y, v.y, sq1);
        sq2 = fmaf(v.z, v.z, sq2); sq3 = fmaf(v.w, v.w, sq3);
    }
    int ci = blk * (D_ / 2) + tid * 2;
    ((float4*)g_cum)[ci]     = make_float4(sx0, sq0, sx1, sq1);
    ((float4*)g_cum)[ci + 1] = make_float4(sx2, sq2, sx3, sq3);

    if (blk == 0) {
        __shared__ float shr[8], she[8];
        float r = 0.f, e = 0.f;
        #pragma unroll
        for (int i = 0; i < 4; i++) {
            int d = tid + i * 256;
            r += fminf(var_fast[d] / fmaxf(var_slow[d], 1e-4f), 10.0f);
            float ev = ema_out[d];
            e = fmaf(ev, ev, e);
        }
        #pragma unroll
        for (int o = 16; o; o >>= 1) {
            r += __shfl_xor_sync(0xffffffffu, r, o);
            e += __shfl_xor_sync(0xffffffffu, e, o);
        }
        if ((tid & 31) == 0) { shr[tid >> 5] = r; she[tid >> 5] = e; }
        __syncthreads();
        if (tid == 0) {
            float rs = 0.f, es = 0.f;
            #pragma unroll
            for (int i = 0; i < 8; i++) { rs += shr[i]; es += she[i]; }
            float tau  = expf(lt[0]);
            float sig1 = log1pf(expf(ls1[0]));
            float sig2 = log1pf(expf(ls2[0]));
            float sig3 = log1pf(expf(ls3[0]));
            float w    = log1pf(expf(lw[0]));
            float a1   = log1pf(expf(la1[0]));
            float a2   = log1pf(expf(la2[0]));
            float a3   = log1pf(expf(la3[0]));
            float burst = fmaxf(rs / (float)D_ - 1.0f, 0.0f);
            float surp2 = tanhf(sig2 * burst);
            float s2p   = powf(fmaxf(surp2, 1e-7f), a2);
            g_scal[0] = tau;  g_scal[1] = w;    g_scal[2] = a1;  g_scal[3] = a3;
            g_scal[4] = sig1; g_scal[5] = sig3; g_scal[6] = s2p;
            g_scal[7] = 1.0f / fmaxf(sqrtf(es), 1e-12f);
        }
    }
}

// ---------------------------------------------------------------------------
// Kernel 2: in-place exclusive scan over sub-chunks, per (b, d)
// ---------------------------------------------------------------------------
__global__ void k_scan() {
    int idx = blockIdx.x * blockDim.x + threadIdx.x;
    int b = idx >> 10;
    int d = idx & (D_ - 1);
    float rx = 0.f, rq = 0.f;
    int base = b * NSUB * D_ + d;
    for (int c0 = 0; c0 < NSUB; c0 += 8) {
        float2 tv[8];
        #pragma unroll
        for (int k = 0; k < 8; k++) tv[k] = g_cum[base + (c0 + k) * D_];
        #pragma unroll
        for (int k = 0; k < 8; k++) {
            g_cum[base + (c0 + k) * D_] = make_float2(rx, rq);
            rx += tv[k].x; rq += tv[k].y;
        }
    }
}

// ---------------------------------------------------------------------------
// Kernel 3: main fused pass, element math in packed f32x2.
// ---------------------------------------------------------------------------
__global__ void __launch_bounds__(THREADS, 4) k_main(const ll2* __restrict__ x,
                                                     const float* __restrict__ ema_mean,
                                                     const float* __restrict__ ema_sq,
                                                     const float* __restrict__ ema_out,
                                                     ll2* __restrict__ out) {
    __shared__ ll2    sG[G][THREADS];    // gelu pairs, 32 KB
    __shared__ float4 smA[G][32];        // per-row 32 partials of (s1,s3,dt,nm)
    int blk = blockIdx.x, tid = threadIdx.x;
    int c = blk & (NCHUNK - 1);
    int lane = tid & 31, wid = tid >> 5;

    float tau  = g_scal[0], w    = g_scal[1], a1  = g_scal[2], a3   = g_scal[3];
    float sig1 = g_scal[4], sig3 = g_scal[5], s2p = g_scal[6], invN = g_scal[7];
    float ws2p = w * s2p;

    const u64 C_G1 = bcast2(0.0356774081363f);
    const u64 C_G0 = bcast2(0.7978845608028654f);
    const u64 C_H  = bcast2(0.5f);

    int d0 = tid * 4;
    u64 A2[2], B2[2], EN2[2], cx2[2], cq2[2];
    #pragma unroll
    for (int p = 0; p < 2; p++) {
        float a_[2], b_[2], e_[2];
        #pragma unroll
        for (int h = 0; h < 2; h++) {
            int d = d0 + p * 2 + h;
            float m = ema_mean[d];
            float v = fmaxf(ema_sq[d] - m * m, 1e-4f);
            float rs = 1.0f / (sqrtf(v) + 1e-5f);
            a_[h] = rs; b_[h] = -m * rs; e_[h] = ema_out[d] * invN;
        }
        A2[p] = pack2(a_[0], a_[1]);
        B2[p] = pack2(b_[0], b_[1]);
        EN2[p] = pack2(e_[0], e_[1]);
    }
    {   // exclusive prefix at this block's first row; g_cum is (x,q) interleaved
        int ci = blk * (D_ / 2) + tid * 2;
        float4 c01 = ((const float4*)g_cum)[ci];
        float4 c23 = ((const float4*)g_cum)[ci + 1];
        cx2[0] = pack2(c01.x, c01.z); cq2[0] = pack2(c01.y, c01.w);
        cx2[1] = pack2(c23.x, c23.z); cq2[1] = pack2(c23.y, c23.w);
    }

    long base = (long)blk * CH * (D_ / 4);
    int t0 = c * CH;

    for (int g = 0; g < CH / G; g++) {
        // ---------- phase A ----------
        #pragma unroll
        for (int r = 0; r < G; r++) {
            int t = t0 + g * G + r;
            float tf  = (float)t;
            float tt4 = (t > 0) ? 1e-4f * tf * tf : 1.0f;   // t=0 -> z3 term 0
            u64 tf2 = bcast2(tf);

            ll2 xv = x[base + (long)(g * G + r) * (D_ / 4) + tid];
            u64 xp[2] = { (u64)xv.x, (u64)xv.y };
            u64 s1a = 0, s3a = 0, dta = 0, nma = 0;   // 0.0 pairs
            ll2 gout;
            #pragma unroll
            for (int p = 0; p < 2; p++) {
                u64 xx = xp[p];
                u64 x2 = mul2(xx, xx);
                u64 q  = fma2(x2, C_G1, C_G0);
                u64 u  = mul2(xx, q);
                float ulo, uhi;
                unpack2(u, ulo, uhi);
                ulo = tanh_fast(ulo);
                uhi = tanh_fast(uhi);
                u64 th = pack2(ulo, uhi);
                u64 h  = mul2(xx, C_H);
                u64 gg = fma2(h, th, h);
                if (p == 0) gout.x = (long long)gg; else gout.y = (long long)gg;
                // s1
                s1a = add2(s1a, abs2(fma2(xx, A2[p], B2[p])));
                // z3 (scaled, division-free, eps dropped)
                u64 P = cx2[p], Q = cq2[p];
                u64 nP = neg2(P);
                u64 dd = fma2(xx, tf2, nP);
                u64 wv = fma2(nP, P, mul2(tf2, Q));
                float wlo, whi;
                unpack2(wv, wlo, whi);
                wlo = rsqrtf(fmaxf(wlo, tt4));
                whi = rsqrtf(fmaxf(whi, tt4));
                u64 rr = pack2(wlo, whi);
                s3a = fma2(abs2(dd), rr, s3a);
                // cosine accumulators
                dta = fma2(gg, EN2[p], dta);
                nma = fma2(gg, gg, nma);
                // causal update
                cx2[p] = add2(P, xx);
                cq2[p] = fma2(xx, xx, Q);
            }
            sG[r][tid] = gout;
            float l0, h0;
            unpack2(s1a, l0, h0); float s1 = l0 + h0;
            unpack2(s3a, l0, h0); float s3 = l0 + h0;
            unpack2(dta, l0, h0); float dt = l0 + h0;
            unpack2(nma, l0, h0); float nm = l0 + h0;
            #pragma unroll
            for (int o = 16; o >= 4; o >>= 1) {
                s1 += __shfl_xor_sync(0xffffffffu, s1, o);
                s3 += __shfl_xor_sync(0xffffffffu, s3, o);
                dt += __shfl_xor_sync(0xffffffffu, dt, o);
                nm += __shfl_xor_sync(0xffffffffu, nm, o);
            }
            if (lane < 4)
                smA[r][wid * 4 + lane] = make_float4(s1, s3, dt, nm);
        }
        __syncthreads();

        // ---------- phase B+C: warp `wid` owns row `wid` completely --------
        {
            float4 v = smA[wid][lane];
            #pragma unroll
            for (int o = 16; o; o >>= 1) {
                v.x += __shfl_xor_sync(0xffffffffu, v.x, o);
                v.y += __shfl_xor_sync(0xffffffffu, v.y, o);
                v.z += __shfl_xor_sync(0xffffffffu, v.z, o);
                v.w += __shfl_xor_sync(0xffffffffu, v.w, o);
            }
            float surp1 = tanh_fast(sig1 * v.x * (1.0f / (float)D_));
            float surp3 = tanh_fast(sig3 * v.y * (1.0f / (float)D_));
            float cs = v.z * rsqrtf(fmaxf(v.w, 1e-24f));
            cs = fminf(fmaxf(cs, -1.0f), 1.0f);
            float gcos = ex2_fast(-1.4426950408889634f * tau * cs);
            float p1 = ex2_fast(a1 * lg2_fast(fmaxf(surp1, 1e-7f)));
            float p3 = ex2_fast(a3 * lg2_fast(fmaxf(surp3, 1e-7f)));
            float gate = gcos * fmaf(ws2p, p1 * p3, 1.0f);
            u64 gate2 = bcast2(gate);

            long rowo = base + (long)(g * G + wid) * (D_ / 4);
            #pragma unroll
            for (int k = 0; k < 8; k++) {
                int idx = lane + k * 32;
                ll2 gg = sG[wid][idx];
                ll2 o2;
                o2.x = (long long)mul2((u64)gg.x, gate2);
                o2.y = (long long)mul2((u64)gg.y, gate2);
                out[rowo + idx] = o2;
            }
        }
        __syncthreads();   // protect sG/smA before next group's phase A
    }
}

// ---------------------------------------------------------------------------
extern "C" void kernel_launch(void* const* d_in, const int* in_sizes, int n_in,
                              void* d_out, int out_size) {
    const float* x        = (const float*)d_in[0];
    const float* ema_mean = (const float*)d_in[1];
    const float* ema_sq   = (const float*)d_in[2];
    const float* ema_out  = (const float*)d_in[3];
    const float* var_fast = (const float*)d_in[4];
    const float* var_slow = (const float*)d_in[5];

    k_partial<<<NBLK2, THREADS>>>((const float4*)x, ema_out, var_fast, var_slow,
                                  (const float*)d_in[6],  (const float*)d_in[7],
                                  (const float*)d_in[8],  (const float*)d_in[9],
                                  (const float*)d_in[10], (const float*)d_in[11],
                                  (const float*)d_in[12], (const float*)d_in[13]);
    k_scan<<<(B_ * D_) / 256, 256>>>();
    k_main<<<NBLK, THREADS>>>((const ll2*)x, ema_mean, ema_sq, ema_out, (ll2*)d_out);
}